// round 8
// baseline (speedup 1.0000x reference)
#include <cuda_runtime.h>
#include <math.h>
#include <stdint.h>

#define LDIM   16
#define HLDIM  512
#define BSZ    128
#define GSZ    100
#define OUTS   8450   // 64 + 1 + 4096 + 64 + 4096 + 64 + 64 + 1

// Scratch (no cudaMalloc allowed)
__device__ float    g_h0[BSZ * HLDIM];
__device__ float    g_h1[BSZ * HLDIM];
__device__ uint32_t g_h2hi[BSZ * HLDIM];   // tf32 hi bits of h2
__device__ uint32_t g_h2lo[BSZ * HLDIM];   // tf32 lo bits of h2
__device__ float    g_wab[BSZ * OUTS];
__device__ float    g_part[8 * BSZ * HLDIM];

// ---------------------------------------------------------------------------
// Helpers
// ---------------------------------------------------------------------------
__device__ __forceinline__ float2 ffma2(float2 a, float2 b, float2 c) {
    float2 d;
    asm("{ .reg .b64 A,B,C,D; mov.b64 A,{%2,%3}; mov.b64 B,{%4,%5};"
        " mov.b64 C,{%6,%7}; fma.rn.f32x2 D,A,B,C; mov.b64 {%0,%1},D; }"
        : "=f"(d.x), "=f"(d.y)
        : "f"(a.x), "f"(a.y), "f"(b.x), "f"(b.y), "f"(c.x), "f"(c.y));
    return d;
}
__device__ __forceinline__ float fast_sin(float x) {
    float k = rintf(x * 0.15915494309189535f);
    float r = fmaf(k, -6.283185307179586f, x);
    return __sinf(r);
}
__device__ __forceinline__ uint32_t tf32_rna(float x) {
    uint32_t r;
    asm("cvt.rna.tf32.f32 %0, %1;" : "=r"(r) : "f"(x));
    return r;
}
__device__ __forceinline__ void tf32_split(float x, uint32_t& hi, uint32_t& lo) {
    hi = tf32_rna(x);
    float r = x - __uint_as_float(hi);
    lo = tf32_rna(r);
}
// m16n8k8 row.col tf32 MMA, fp32 accumulate (HMMA — plain compute_100 legal)
__device__ __forceinline__ void mma_tf32(float* c,
                                         uint32_t a0, uint32_t a1,
                                         uint32_t a2, uint32_t a3,
                                         uint32_t b0, uint32_t b1) {
    asm volatile(
        "mma.sync.aligned.m16n8k8.row.col.f32.tf32.tf32.f32 "
        "{%0,%1,%2,%3}, {%4,%5,%6,%7}, {%8,%9}, {%0,%1,%2,%3};"
        : "+f"(c[0]), "+f"(c[1]), "+f"(c[2]), "+f"(c[3])
        : "r"(a0), "r"(a1), "r"(a2), "r"(a3), "r"(b0), "r"(b1));
}

// ----------------------------------------------------------------------------
// wab GEMM on tensor pipe: wab[128,8450] = h2 @ hWo + hbo   (3xTF32 split)
// 133 CTAs x 256 threads (8 warps). Warp w owns rows [16w,16w+16), 64 cols.
// K chunked 32: B chunk split to smem (stride 72, conflict-free), prefetched.
// A fragments read from pre-split g_h2hi/g_h2lo (L2-resident).
// ----------------------------------------------------------------------------
#define BSTRIDE 72
__global__ __launch_bounds__(256)
void wab_mma(const float* __restrict__ hWo,
             const float* __restrict__ hbo,
             float* __restrict__ wab)
{
    __shared__ uint32_t BsH[32 * BSTRIDE];
    __shared__ uint32_t BsL[32 * BSTRIDE];

    const int t = threadIdx.x;
    const int wid = t >> 5, lane = t & 31;
    const int g = lane >> 2, tig = lane & 3;
    const int n0 = blockIdx.x * 64;
    const int m0 = wid * 16;

    float acc[8][4];
#pragma unroll
    for (int nt = 0; nt < 8; nt++)
#pragma unroll
        for (int i = 0; i < 4; i++) acc[nt][i] = 0.0f;

    float pre[8];
    auto load_chunk = [&](int ch) {
#pragma unroll
        for (int q = 0; q < 8; q++) {
            int idx = q * 256 + t;
            int k = idx >> 6, n = idx & 63;
            int gn = n0 + n;
            pre[q] = (gn < OUTS)
                   ? __ldg(&hWo[(size_t)(ch * 32 + k) * OUTS + gn]) : 0.0f;
        }
    };
    auto store_chunk = [&]() {
#pragma unroll
        for (int q = 0; q < 8; q++) {
            int idx = q * 256 + t;
            int k = idx >> 6, n = idx & 63;
            uint32_t h, l;
            tf32_split(pre[q], h, l);
            BsH[k * BSTRIDE + n] = h;
            BsL[k * BSTRIDE + n] = l;
        }
    };

    load_chunk(0);
    for (int ch = 0; ch < 16; ch++) {
        store_chunk();
        __syncthreads();
        if (ch < 15) load_chunk(ch + 1);

#pragma unroll
        for (int ks = 0; ks < 4; ks++) {
            const int kk0 = ch * 32 + ks * 8;
            const int r0 = (m0 + g) * 512 + kk0 + tig;
            const int r8 = (m0 + g + 8) * 512 + kk0 + tig;
            uint32_t ah0 = __ldg(&g_h2hi[r0]);
            uint32_t ah1 = __ldg(&g_h2hi[r8]);
            uint32_t ah2 = __ldg(&g_h2hi[r0 + 4]);
            uint32_t ah3 = __ldg(&g_h2hi[r8 + 4]);
            uint32_t al0 = __ldg(&g_h2lo[r0]);
            uint32_t al1 = __ldg(&g_h2lo[r8]);
            uint32_t al2 = __ldg(&g_h2lo[r0 + 4]);
            uint32_t al3 = __ldg(&g_h2lo[r8 + 4]);

            const int br0 = (ks * 8 + tig) * BSTRIDE + g;
            const int br1 = (ks * 8 + tig + 4) * BSTRIDE + g;
#pragma unroll
            for (int nt = 0; nt < 8; nt++) {
                uint32_t b0h = BsH[br0 + nt * 8];
                uint32_t b1h = BsH[br1 + nt * 8];
                uint32_t b0l = BsL[br0 + nt * 8];
                uint32_t b1l = BsL[br1 + nt * 8];
                mma_tf32(acc[nt], ah0, ah1, ah2, ah3, b0h, b1h);
                mma_tf32(acc[nt], ah0, ah1, ah2, ah3, b0l, b1l);
                mma_tf32(acc[nt], al0, al1, al2, al3, b0h, b1h);
            }
        }
        __syncthreads();
    }

    // epilogue: c0:(g, 2*tig) c1:(g, 2*tig+1) c2:(g+8, 2*tig) c3:(g+8, 2*tig+1)
#pragma unroll
    for (int nt = 0; nt < 8; nt++) {
        int col = n0 + nt * 8 + 2 * tig;
        int row0 = m0 + g, row8 = m0 + g + 8;
        if (col < OUTS) {
            float bb = __ldg(&hbo[col]);
            wab[(size_t)row0 * OUTS + col] = acc[nt][0] + bb;
            wab[(size_t)row8 * OUTS + col] = acc[nt][2] + bb;
        }
        if (col + 1 < OUTS) {
            float bb = __ldg(&hbo[col + 1]);
            wab[(size_t)row0 * OUTS + col + 1] = acc[nt][1] + bb;
            wab[(size_t)row8 * OUTS + col + 1] = acc[nt][3] + bb;
        }
    }
}

// ----------------------------------------------------------------------------
// Double-buffered fp32 GEMM (FFMA2) with split-K — h1/h2
// ----------------------------------------------------------------------------
template<int BM, int BN, int BK, int TM, int TN, int SPLITS>
__launch_bounds__((BM / TM) * (BN / TN))
__global__ void gemm_db(const float* __restrict__ A,
                        const float* __restrict__ B,
                        float* __restrict__ C,
                        int M, int N, int K)
{
    constexpr int NT = (BM / TM) * (BN / TN);
    constexpr int APT = (BM * BK) / (4 * NT);
    constexpr int BPT = (BK * BN) / (2 * NT);

    __shared__ float As[BK][BM + 4];
    __shared__ float Bs[BK][BN];

    const int bm = blockIdx.y * BM;
    const int bn = blockIdx.x * BN;
    const int tid = threadIdx.x;
    const int tc = (tid % (BN / TN)) * TN;
    const int tr = (tid / (BN / TN)) * TM;
    const int Kc = K / SPLITS;
    const int kbase = blockIdx.z * Kc;

    float4 aReg[APT];
    float2 bReg[BPT];

    auto load_tiles = [&](int k0) {
#pragma unroll
        for (int q = 0; q < APT; q++) {
            int idx = tid + q * NT;
            int m = idx / (BK / 4);
            int kq = idx % (BK / 4);
            aReg[q] = *(const float4*)&A[(size_t)(bm + m) * K + kbase + k0 + kq * 4];
        }
#pragma unroll
        for (int q = 0; q < BPT; q++) {
            int idx = tid + q * NT;
            int kk = idx / (BN / 2);
            int c2 = idx % (BN / 2);
            bReg[q] = *(const float2*)&B[(size_t)(kbase + k0 + kk) * N + bn + c2 * 2];
        }
    };
    auto store_tiles = [&]() {
#pragma unroll
        for (int q = 0; q < APT; q++) {
            int idx = tid + q * NT;
            int m = idx / (BK / 4);
            int kq = idx % (BK / 4);
            As[kq * 4 + 0][m] = aReg[q].x;
            As[kq * 4 + 1][m] = aReg[q].y;
            As[kq * 4 + 2][m] = aReg[q].z;
            As[kq * 4 + 3][m] = aReg[q].w;
        }
#pragma unroll
        for (int q = 0; q < BPT; q++) {
            int idx = tid + q * NT;
            int kk = idx / (BN / 2);
            int c2 = idx % (BN / 2);
            *(float2*)&Bs[kk][c2 * 2] = bReg[q];
        }
    };

    float2 acc[TM][TN / 2];
#pragma unroll
    for (int i = 0; i < TM; i++)
#pragma unroll
        for (int j = 0; j < TN / 2; j++) acc[i][j] = make_float2(0.f, 0.f);

    load_tiles(0);
    for (int k0 = 0; k0 < Kc; k0 += BK) {
        store_tiles();
        __syncthreads();
        if (k0 + BK < Kc) load_tiles(k0 + BK);
#pragma unroll
        for (int kk = 0; kk < BK; kk++) {
            float av[TM];
            float2 bv[TN / 2];
#pragma unroll
            for (int i = 0; i < TM; i += 2) {
                float2 v = *(const float2*)&As[kk][tr + i];
                av[i] = v.x; av[i + 1] = v.y;
            }
#pragma unroll
            for (int j = 0; j < TN / 4; j++) {
                float4 v = *(const float4*)&Bs[kk][tc + j * 4];
                bv[j * 2 + 0] = make_float2(v.x, v.y);
                bv[j * 2 + 1] = make_float2(v.z, v.w);
            }
#pragma unroll
            for (int i = 0; i < TM; i++) {
                float2 a2 = make_float2(av[i], av[i]);
#pragma unroll
                for (int j = 0; j < TN / 2; j++)
                    acc[i][j] = ffma2(a2, bv[j], acc[i][j]);
            }
        }
        __syncthreads();
    }

    float* __restrict__ P = C + (size_t)blockIdx.z * M * N;
#pragma unroll
    for (int i = 0; i < TM; i++) {
        int gm = bm + tr + i;
#pragma unroll
        for (int j = 0; j < TN / 2; j++)
            *(float2*)&P[(size_t)gm * N + bn + tc + j * 2] = acc[i][j];
    }
}

// ----------------------------------------------------------------------------
// h0: h0[128,512] = leaky(z[128,16] @ hW0[16,512] + hb0)
// ----------------------------------------------------------------------------
__global__ __launch_bounds__(256)
void h0_kernel(const float* __restrict__ z,
               const float* __restrict__ hW0,
               const float* __restrict__ hb0,
               float* __restrict__ h0)
{
    const int t = threadIdx.x;
    const int n0 = blockIdx.x * 4 + (t >> 7) * 2;
    const int m = t & 127;
    float2 acc = make_float2(0.f, 0.f);
#pragma unroll
    for (int k = 0; k < 16; k++) {
        float a = __ldg(&z[m * 16 + k]);
        float2 w = __ldg((const float2*)&hW0[k * 512 + n0]);
        acc = ffma2(make_float2(a, a), w, acc);
    }
    float2 bb = __ldg((const float2*)&hb0[n0]);
    float vx = acc.x + bb.x; vx = (vx > 0.f) ? vx : 0.01f * vx;
    float vy = acc.y + bb.y; vy = (vy > 0.f) ? vy : 0.01f * vy;
    *(float2*)&h0[m * 512 + n0] = make_float2(vx, vy);
}

// ----------------------------------------------------------------------------
// Split-K reduce + bias + leaky -> float out (h1)
// ----------------------------------------------------------------------------
template<int SPLITS>
__global__ void reduce_bias(const float* __restrict__ P,
                            const float* __restrict__ bias,
                            float* __restrict__ C, int M, int N)
{
    int i = blockIdx.x * blockDim.x + threadIdx.x;
    int MN = M * N;
    if (i >= MN) return;
    float s = 0.0f;
#pragma unroll
    for (int z = 0; z < SPLITS; z++) s += P[(size_t)z * MN + i];
    s += bias[i % N];
    s = (s > 0.0f) ? s : 0.01f * s;
    C[i] = s;
}

// Split-K reduce + bias + leaky -> tf32 hi/lo split (h2, feeds wab_mma)
template<int SPLITS>
__global__ void reduce_bias_split(const float* __restrict__ P,
                                  const float* __restrict__ bias,
                                  uint32_t* __restrict__ Chi,
                                  uint32_t* __restrict__ Clo,
                                  int M, int N)
{
    int i = blockIdx.x * blockDim.x + threadIdx.x;
    int MN = M * N;
    if (i >= MN) return;
    float s = 0.0f;
#pragma unroll
    for (int z = 0; z < SPLITS; z++) s += P[(size_t)z * MN + i];
    s += bias[i % N];
    s = (s > 0.0f) ? s : 0.01f * s;
    uint32_t h, l;
    tf32_split(s, h, l);
    Chi[i] = h;
    Clo[i] = l;
}

// ----------------------------------------------------------------------------
// Decoder: one block per b, 512 threads = 4 j-groups x 128 g-lanes, MUFU sin.
// ----------------------------------------------------------------------------
#define DEC_NT 512
#define DEC_SMEM_FLOATS (8452 + 64 * 128)

__global__ __launch_bounds__(DEC_NT)
void decoder_kernel(const float* __restrict__ logP,
                    const float* __restrict__ wab,
                    float* __restrict__ out)
{
    extern __shared__ float s[];
    float* s_w0 = s;
    float* s_W1 = s + 64;
    float* s_W2 = s + 4160;
    float* s_w3 = s + 8256;
    float* s_b1 = s + 8320;
    float* s_b2 = s + 8384;
    float* s_sc = s + 8448;
    float* s_x  = s + 8452;

    const int b = blockIdx.x;
    const int tid = threadIdx.x;
    const float* __restrict__ src = wab + (size_t)b * OUTS;

    if (tid < 64) {
        s_w0[tid] = src[tid];
        s_b1[tid] = src[4161 + tid];
        s_b2[tid] = src[8321 + tid];
        s_w3[tid] = src[8385 + tid];
    }
    for (int i = tid; i < 4096; i += DEC_NT) {
        s_W1[i] = src[65 + i];
        s_W2[i] = src[4225 + i];
    }
    if (tid == 0) { s_sc[0] = src[64]; s_sc[1] = src[8449]; }
    __syncthreads();

    const int lane = tid & 127;
    const int grp = tid >> 7;
    const int j0 = grp * 16;
    const bool active = (lane < GSZ);
    float x_in = 0.0f;
    if (active) x_in = logP[b * GSZ + lane] * (1.0f / 3.0f);
    const float b0 = s_sc[0];
    const float b3 = s_sc[1];

    if (active) {
#pragma unroll
        for (int jj = 0; jj < 16; jj++) {
            float v = 30.0f * fmaf(x_in, s_w0[j0 + jj], b0);
            s_x[(j0 + jj) * 128 + lane] = fast_sin(v);
        }
    }
    __syncthreads();

    float2 acc[8];

    // layer 1
    if (active) {
#pragma unroll
        for (int q = 0; q < 8; q++) acc[q] = *(float2*)&s_b1[j0 + q * 2];
#pragma unroll 8
        for (int i = 0; i < 64; i++) {
            float a = s_x[i * 128 + lane];
            float2 a2 = make_float2(a, a);
#pragma unroll
            for (int q = 0; q < 4; q++) {
                float4 w = *(float4*)&s_W1[i * 64 + j0 + q * 4];
                acc[q * 2 + 0] = ffma2(a2, make_float2(w.x, w.y), acc[q * 2 + 0]);
                acc[q * 2 + 1] = ffma2(a2, make_float2(w.z, w.w), acc[q * 2 + 1]);
            }
        }
    }
    __syncthreads();
    if (active) {
#pragma unroll
        for (int q = 0; q < 8; q++) {
            s_x[(j0 + q * 2 + 0) * 128 + lane] = fast_sin(acc[q].x);
            s_x[(j0 + q * 2 + 1) * 128 + lane] = fast_sin(acc[q].y);
        }
    }
    __syncthreads();

    // layer 2
    if (active) {
#pragma unroll
        for (int q = 0; q < 8; q++) acc[q] = *(float2*)&s_b2[j0 + q * 2];
#pragma unroll 8
        for (int i = 0; i < 64; i++) {
            float a = s_x[i * 128 + lane];
            float2 a2 = make_float2(a, a);
#pragma unroll
            for (int q = 0; q < 4; q++) {
                float4 w = *(float4*)&s_W2[i * 64 + j0 + q * 4];
                acc[q * 2 + 0] = ffma2(a2, make_float2(w.x, w.y), acc[q * 2 + 0]);
                acc[q * 2 + 1] = ffma2(a2, make_float2(w.z, w.w), acc[q * 2 + 1]);
            }
        }
    }
    __syncthreads();
    if (active) {
#pragma unroll
        for (int q = 0; q < 8; q++) {
            s_x[(j0 + q * 2 + 0) * 128 + lane] = fast_sin(acc[q].x);
            s_x[(j0 + q * 2 + 1) * 128 + lane] = fast_sin(acc[q].y);
        }
    }
    __syncthreads();

    if (grp == 0 && active) {
        float o = b3;
#pragma unroll 8
        for (int i = 0; i < 64; i++)
            o = fmaf(s_x[i * 128 + lane], s_w3[i], o);
        out[b * GSZ + lane] = fmaf(o, 500.0f, 1500.0f);
    }
}

// ----------------------------------------------------------------------------
extern "C" void kernel_launch(void* const* d_in, const int* in_sizes, int n_in,
                              void* d_out, int out_size)
{
    const float* z    = (const float*)d_in[0];
    const float* logP = (const float*)d_in[1];
    const float* hW0  = (const float*)d_in[2];
    const float* hb0  = (const float*)d_in[3];
    const float* hW1  = (const float*)d_in[4];
    const float* hb1  = (const float*)d_in[5];
    const float* hW2  = (const float*)d_in[6];
    const float* hb2  = (const float*)d_in[7];
    const float* hWo  = (const float*)d_in[8];
    const float* hbo  = (const float*)d_in[9];
    float* out = (float*)d_out;

    float *h0p, *h1p, *wabp, *partp;
    uint32_t *h2hip, *h2lop;
    cudaGetSymbolAddress((void**)&h0p, g_h0);
    cudaGetSymbolAddress((void**)&h1p, g_h1);
    cudaGetSymbolAddress((void**)&h2hip, g_h2hi);
    cudaGetSymbolAddress((void**)&h2lop, g_h2lo);
    cudaGetSymbolAddress((void**)&wabp, g_wab);
    cudaGetSymbolAddress((void**)&partp, g_part);

    static int configured = 0;
    if (!configured) {
        cudaFuncSetAttribute(decoder_kernel,
                             cudaFuncAttributeMaxDynamicSharedMemorySize,
                             DEC_SMEM_FLOATS * (int)sizeof(float));
        configured = 1;
    }

    // h0
    h0_kernel<<<128, 256>>>(z, hW0, hb0, h0p);

    // h1: split-K x8, double-buffered FFMA2
    gemm_db<32, 64, 32, 2, 4, 8><<<dim3(HLDIM / 64, BSZ / 32, 8), 256>>>(
        h0p, hW1, partp, BSZ, HLDIM, HLDIM);
    reduce_bias<8><<<(BSZ * HLDIM + 255) / 256, 256>>>(
        partp, hb1, h1p, BSZ, HLDIM);

    // h2 (reduce fuses tf32 hi/lo split for the MMA consumer)
    gemm_db<32, 64, 32, 2, 4, 8><<<dim3(HLDIM / 64, BSZ / 32, 8), 256>>>(
        h1p, hW2, partp, BSZ, HLDIM, HLDIM);
    reduce_bias_split<8><<<(BSZ * HLDIM + 255) / 256, 256>>>(
        partp, hb2, h2hip, h2lop, BSZ, HLDIM);

    // wab on the tensor pipe (mma.sync tf32, 3-term split), bias fused
    wab_mma<<<(OUTS + 63) / 64, 256>>>(hWo, hbo, wabp);

    // decoder
    decoder_kernel<<<BSZ, DEC_NT, DEC_SMEM_FLOATS * (int)sizeof(float)>>>(
        logP, wabp, out);
}

// round 9
// speedup vs baseline: 1.1956x; 1.1956x over previous
#include <cuda_runtime.h>
#include <math.h>

#define LDIM   16
#define HLDIM  512
#define BSZ    128
#define GSZ    100
#define OUTS   8450   // 64 + 1 + 4096 + 64 + 4096 + 64 + 64 + 1

// Scratch (no cudaMalloc allowed)
__device__ float g_h0[BSZ * HLDIM];
__device__ float g_h1[BSZ * HLDIM];
__device__ float g_h2[BSZ * HLDIM];
__device__ float g_part[8 * BSZ * HLDIM > 2 * BSZ * OUTS ? 8 * BSZ * HLDIM
                                                         : 2 * BSZ * OUTS];

// ---------------------------------------------------------------------------
// Packed fp32x2 FMA (Blackwell) — 2 exact fp32 MACs per issue slot
// ---------------------------------------------------------------------------
__device__ __forceinline__ float2 ffma2(float2 a, float2 b, float2 c) {
    float2 d;
    asm("{ .reg .b64 A,B,C,D; mov.b64 A,{%2,%3}; mov.b64 B,{%4,%5};"
        " mov.b64 C,{%6,%7}; fma.rn.f32x2 D,A,B,C; mov.b64 {%0,%1},D; }"
        : "=f"(d.x), "=f"(d.y)
        : "f"(a.x), "f"(a.y), "f"(b.x), "f"(b.y), "f"(c.x), "f"(c.y));
    return d;
}

// ---------------------------------------------------------------------------
// FMA-pipe sine: Cody-Waite pi reduction + degree-9 minimax poly.
// ~10 FMA/ALU ops; avoids the 0.5/cyc/SM MUFU bottleneck.
// ---------------------------------------------------------------------------
__device__ __forceinline__ float sin_poly(float x) {
    float kf = rintf(x * 0.318309886183790672f);     // x / pi
    int ki = (int)kf;
    float r = fmaf(kf, -3.14159274101257324f, x);    // x - k*pi_hi (pi_hi = fp32 pi)
    r = fmaf(kf, 8.74227765734758577e-8f, r);        // + k*(pi_hi - pi)
    float r2 = r * r;
    float p = fmaf(r2, 2.7525562e-6f, -1.9826217e-4f);
    p = fmaf(r2, p, 8.3333310e-3f);
    p = fmaf(r2, p, -1.66666667e-1f);
    float s = fmaf(r * r2, p, r);
    return __int_as_float(__float_as_int(s) ^ ((ki & 1) << 31));
}

// ----------------------------------------------------------------------------
// Double-buffered fp32 GEMM (FFMA2 inner) with optional split-K.
// SPLITS>1: raw partials to C[z][M][N].
// ----------------------------------------------------------------------------
template<int BM, int BN, int BK, int TM, int TN, int SPLITS>
__launch_bounds__((BM / TM) * (BN / TN))
__global__ void gemm_db(const float* __restrict__ A,
                        const float* __restrict__ B,
                        float* __restrict__ C,
                        int M, int N, int K)
{
    constexpr int NT = (BM / TM) * (BN / TN);
    constexpr int APT = (BM * BK) / (4 * NT);
    constexpr int BPT = (BK * BN) / (2 * NT);

    __shared__ float As[BK][BM + 4];
    __shared__ float Bs[BK][BN];

    const int bm = blockIdx.y * BM;
    const int bn = blockIdx.x * BN;
    const int tid = threadIdx.x;
    const int tc = (tid % (BN / TN)) * TN;
    const int tr = (tid / (BN / TN)) * TM;
    const int Kc = K / SPLITS;
    const int kbase = blockIdx.z * Kc;

    float4 aReg[APT];
    float2 bReg[BPT];

    auto load_tiles = [&](int k0) {
#pragma unroll
        for (int q = 0; q < APT; q++) {
            int idx = tid + q * NT;
            int m = idx / (BK / 4);
            int kq = idx % (BK / 4);
            aReg[q] = *(const float4*)&A[(size_t)(bm + m) * K + kbase + k0 + kq * 4];
        }
#pragma unroll
        for (int q = 0; q < BPT; q++) {
            int idx = tid + q * NT;
            int kk = idx / (BN / 2);
            int c2 = idx % (BN / 2);
            int gc = bn + c2 * 2;
            float2 v = make_float2(0.f, 0.f);
            if (gc + 2 <= N)
                v = *(const float2*)&B[(size_t)(kbase + k0 + kk) * N + gc];
            bReg[q] = v;
        }
    };
    auto store_tiles = [&]() {
#pragma unroll
        for (int q = 0; q < APT; q++) {
            int idx = tid + q * NT;
            int m = idx / (BK / 4);
            int kq = idx % (BK / 4);
            As[kq * 4 + 0][m] = aReg[q].x;
            As[kq * 4 + 1][m] = aReg[q].y;
            As[kq * 4 + 2][m] = aReg[q].z;
            As[kq * 4 + 3][m] = aReg[q].w;
        }
#pragma unroll
        for (int q = 0; q < BPT; q++) {
            int idx = tid + q * NT;
            int kk = idx / (BN / 2);
            int c2 = idx % (BN / 2);
            *(float2*)&Bs[kk][c2 * 2] = bReg[q];
        }
    };

    float2 acc[TM][TN / 2];
#pragma unroll
    for (int i = 0; i < TM; i++)
#pragma unroll
        for (int j = 0; j < TN / 2; j++) acc[i][j] = make_float2(0.f, 0.f);

    load_tiles(0);
    for (int k0 = 0; k0 < Kc; k0 += BK) {
        store_tiles();
        __syncthreads();
        if (k0 + BK < Kc) load_tiles(k0 + BK);
#pragma unroll
        for (int kk = 0; kk < BK; kk++) {
            float av[TM];
            float2 bv[TN / 2];
#pragma unroll
            for (int i = 0; i < TM; i += 2) {
                float2 v = *(const float2*)&As[kk][tr + i];
                av[i] = v.x; av[i + 1] = v.y;
            }
#pragma unroll
            for (int j = 0; j < TN / 4; j++) {
                float4 v = *(const float4*)&Bs[kk][tc + j * 4];
                bv[j * 2 + 0] = make_float2(v.x, v.y);
                bv[j * 2 + 1] = make_float2(v.z, v.w);
            }
#pragma unroll
            for (int i = 0; i < TM; i++) {
                float2 a2 = make_float2(av[i], av[i]);
#pragma unroll
                for (int j = 0; j < TN / 2; j++)
                    acc[i][j] = ffma2(a2, bv[j], acc[i][j]);
            }
        }
        __syncthreads();
    }

    float* __restrict__ P = C + (size_t)blockIdx.z * M * N;
#pragma unroll
    for (int i = 0; i < TM; i++) {
        int gm = bm + tr + i;
#pragma unroll
        for (int j = 0; j < TN / 2; j++) {
            int gn = bn + tc + j * 2;
            if (gn + 2 <= N) {
                *(float2*)&P[(size_t)gm * N + gn] = acc[i][j];
            } else if (gn < N) {
                P[(size_t)gm * N + gn] = acc[i][j].x;
            }
        }
    }
}

// ----------------------------------------------------------------------------
// h0: h0[128,512] = leaky(z[128,16] @ hW0[16,512] + hb0)
// ----------------------------------------------------------------------------
__global__ __launch_bounds__(256)
void h0_kernel(const float* __restrict__ z,
               const float* __restrict__ hW0,
               const float* __restrict__ hb0,
               float* __restrict__ h0)
{
    const int t = threadIdx.x;
    const int n0 = blockIdx.x * 4 + (t >> 7) * 2;
    const int m = t & 127;
    float2 acc = make_float2(0.f, 0.f);
#pragma unroll
    for (int k = 0; k < 16; k++) {
        float a = __ldg(&z[m * 16 + k]);
        float2 w = __ldg((const float2*)&hW0[k * 512 + n0]);
        acc = ffma2(make_float2(a, a), w, acc);
    }
    float2 bb = __ldg((const float2*)&hb0[n0]);
    float vx = acc.x + bb.x; vx = (vx > 0.f) ? vx : 0.01f * vx;
    float vy = acc.y + bb.y; vy = (vy > 0.f) ? vy : 0.01f * vy;
    *(float2*)&h0[m * 512 + n0] = make_float2(vx, vy);
}

// ----------------------------------------------------------------------------
// Split-K reduce + bias + leaky (h1/h2)
// ----------------------------------------------------------------------------
template<int SPLITS>
__global__ void reduce_bias(const float* __restrict__ P,
                            const float* __restrict__ bias,
                            float* __restrict__ C, int M, int N)
{
    int i = blockIdx.x * blockDim.x + threadIdx.x;
    int MN = M * N;
    if (i >= MN) return;
    float s = 0.0f;
#pragma unroll
    for (int z = 0; z < SPLITS; z++) s += P[(size_t)z * MN + i];
    s += bias[i % N];
    s = (s > 0.0f) ? s : 0.01f * s;
    C[i] = s;
}

// ----------------------------------------------------------------------------
// Decoder with fused wab split-K(x2) reduce. One block per b,
// 512 threads = 4 j-groups x 128 g-lanes. FMA-pipe polynomial sines.
// ----------------------------------------------------------------------------
#define DEC_NT 512
#define DEC_SMEM_FLOATS (8452 + 8452 + 64 * 128)

__global__ __launch_bounds__(DEC_NT)
void decoder_kernel(const float* __restrict__ logP,
                    const float* __restrict__ part,
                    const float* __restrict__ hbo,
                    float* __restrict__ out)
{
    extern __shared__ float s[];
    float* s_row = s;
    float* s_wgt = s + 8452;
    float* s_x   = s + 8452 + 8452;

    float* s_w0 = s_wgt;
    float* s_W1 = s_wgt + 64;
    float* s_W2 = s_wgt + 4160;
    float* s_w3 = s_wgt + 8256;
    float* s_b1 = s_wgt + 8320;
    float* s_b2 = s_wgt + 8384;
    float* s_sc = s_wgt + 8448;

    const int b = blockIdx.x;
    const int tid = threadIdx.x;

    // stage: wab_row[i] = part[0][b][i] + part[1][b][i] + hbo[i]
    {
        const float2* bias2 = (const float2*)hbo;
        const float2* p0 = (const float2*)(part + (size_t)b * OUTS);
        const size_t zs = (size_t)BSZ * OUTS / 2;
        float2* row2 = (float2*)s_row;
        for (int i = tid; i < OUTS / 2; i += DEC_NT) {
            float2 a = bias2[i];
            float2 v0 = p0[i];
            float2 v1 = p0[i + zs];
            a.x += v0.x + v1.x;
            a.y += v0.y + v1.y;
            row2[i] = a;
        }
    }
    __syncthreads();

    if (tid < 64) {
        s_w0[tid] = s_row[tid];
        s_b1[tid] = s_row[4161 + tid];
        s_b2[tid] = s_row[8321 + tid];
        s_w3[tid] = s_row[8385 + tid];
    }
    for (int i = tid; i < 4096; i += DEC_NT) {
        s_W1[i] = s_row[65 + i];
        s_W2[i] = s_row[4225 + i];
    }
    if (tid == 0) { s_sc[0] = s_row[64]; s_sc[1] = s_row[8449]; }
    __syncthreads();

    const int lane = tid & 127;
    const int grp = tid >> 7;          // 0..3
    const int j0 = grp * 16;
    const bool active = (lane < GSZ);
    float x_in = 0.0f;
    if (active) x_in = logP[b * GSZ + lane] * (1.0f / 3.0f);
    const float b0 = s_sc[0];
    const float b3 = s_sc[1];

    if (active) {
#pragma unroll
        for (int jj = 0; jj < 16; jj++) {
            float v = 30.0f * fmaf(x_in, s_w0[j0 + jj], b0);
            s_x[(j0 + jj) * 128 + lane] = sin_poly(v);
        }
    }
    __syncthreads();

    float2 acc[8];

    // layer 1
    if (active) {
#pragma unroll
        for (int q = 0; q < 8; q++) acc[q] = *(float2*)&s_b1[j0 + q * 2];
#pragma unroll 8
        for (int i = 0; i < 64; i++) {
            float a = s_x[i * 128 + lane];
            float2 a2 = make_float2(a, a);
#pragma unroll
            for (int q = 0; q < 4; q++) {
                float4 w = *(float4*)&s_W1[i * 64 + j0 + q * 4];
                acc[q * 2 + 0] = ffma2(a2, make_float2(w.x, w.y), acc[q * 2 + 0]);
                acc[q * 2 + 1] = ffma2(a2, make_float2(w.z, w.w), acc[q * 2 + 1]);
            }
        }
    }
    __syncthreads();
    if (active) {
#pragma unroll
        for (int q = 0; q < 8; q++) {
            s_x[(j0 + q * 2 + 0) * 128 + lane] = sin_poly(acc[q].x);
            s_x[(j0 + q * 2 + 1) * 128 + lane] = sin_poly(acc[q].y);
        }
    }
    __syncthreads();

    // layer 2
    if (active) {
#pragma unroll
        for (int q = 0; q < 8; q++) acc[q] = *(float2*)&s_b2[j0 + q * 2];
#pragma unroll 8
        for (int i = 0; i < 64; i++) {
            float a = s_x[i * 128 + lane];
            float2 a2 = make_float2(a, a);
#pragma unroll
            for (int q = 0; q < 4; q++) {
                float4 w = *(float4*)&s_W2[i * 64 + j0 + q * 4];
                acc[q * 2 + 0] = ffma2(a2, make_float2(w.x, w.y), acc[q * 2 + 0]);
                acc[q * 2 + 1] = ffma2(a2, make_float2(w.z, w.w), acc[q * 2 + 1]);
            }
        }
    }
    __syncthreads();
    if (active) {
#pragma unroll
        for (int q = 0; q < 8; q++) {
            s_x[(j0 + q * 2 + 0) * 128 + lane] = sin_poly(acc[q].x);
            s_x[(j0 + q * 2 + 1) * 128 + lane] = sin_poly(acc[q].y);
        }
    }
    __syncthreads();

    // layer 3 (scalar out): group 0 reduces
    if (grp == 0 && active) {
        float o = b3;
#pragma unroll 8
        for (int i = 0; i < 64; i++)
            o = fmaf(s_x[i * 128 + lane], s_w3[i], o);
        out[b * GSZ + lane] = fmaf(o, 500.0f, 1500.0f);
    }
}

// ----------------------------------------------------------------------------
extern "C" void kernel_launch(void* const* d_in, const int* in_sizes, int n_in,
                              void* d_out, int out_size)
{
    const float* z    = (const float*)d_in[0];
    const float* logP = (const float*)d_in[1];
    const float* hW0  = (const float*)d_in[2];
    const float* hb0  = (const float*)d_in[3];
    const float* hW1  = (const float*)d_in[4];
    const float* hb1  = (const float*)d_in[5];
    const float* hW2  = (const float*)d_in[6];
    const float* hb2  = (const float*)d_in[7];
    const float* hWo  = (const float*)d_in[8];
    const float* hbo  = (const float*)d_in[9];
    float* out = (float*)d_out;

    float *h0p, *h1p, *h2p, *partp;
    cudaGetSymbolAddress((void**)&h0p, g_h0);
    cudaGetSymbolAddress((void**)&h1p, g_h1);
    cudaGetSymbolAddress((void**)&h2p, g_h2);
    cudaGetSymbolAddress((void**)&partp, g_part);

    static int configured = 0;
    if (!configured) {
        cudaFuncSetAttribute(decoder_kernel,
                             cudaFuncAttributeMaxDynamicSharedMemorySize,
                             DEC_SMEM_FLOATS * (int)sizeof(float));
        configured = 1;
    }

    // h0: 128x512x16
    h0_kernel<<<128, 256>>>(z, hW0, hb0, h0p);

    // h1: 128x512x512, split-K x8, double-buffered
    gemm_db<32, 64, 32, 2, 4, 8><<<dim3(HLDIM / 64, BSZ / 32, 8), 256>>>(
        h0p, hW1, partp, BSZ, HLDIM, HLDIM);
    reduce_bias<8><<<(BSZ * HLDIM + 255) / 256, 256>>>(
        partp, hb1, h1p, BSZ, HLDIM);

    // h2
    gemm_db<32, 64, 32, 2, 4, 8><<<dim3(HLDIM / 64, BSZ / 32, 8), 256>>>(
        h1p, hW2, partp, BSZ, HLDIM, HLDIM);
    reduce_bias<8><<<(BSZ * HLDIM + 255) / 256, 256>>>(
        partp, hb2, h2p, BSZ, HLDIM);

    // wab: 128x8450x512, split-K x2 -> 134 CTAs, 16 pipelined k-iters
    gemm_db<128, 128, 16, 8, 8, 2><<<dim3((OUTS + 127) / 128, 1, 2), 256>>>(
        h2p, hWo, partp, BSZ, OUTS, HLDIM);

    // decoder (fused wab reduce, polynomial sines)
    const int smem_bytes = DEC_SMEM_FLOATS * (int)sizeof(float);
    decoder_kernel<<<BSZ, DEC_NT, smem_bytes>>>(logP, partp, hbo, out);
}